// round 8
// baseline (speedup 1.0000x reference)
#include <cuda_runtime.h>

// SpectralConv1D: out = irfft( pad( rfft(x)[:, :32, :] @ W ) )
// Quad-folded trig transforms (4x via mirror symmetry over
// {s, 2048-s, 2048+s, 4096-s}). B=64, S=4096, Cin=Cout=64, MODES=32.

#define S_TOT   4096
#define SMASK   4095
#define CIN     64
#define COUT    64
#define MODES   32
#define NB      64
#define CH_A    8
#define SUBS    2
#define NCH     (CH_A*SUBS)
#define QPB_A   128
#define STG_A   16
#define NSTG    (QPB_A/STG_A)
#define QPB_C   64

typedef unsigned long long ull;

__device__ float2 g_tw[S_TOT];                      // (cos,sin)(2*pi*j/4096)
__device__ float2 g_Yp[NCH][NB][MODES][CIN];        // split-K partials (Cr,Si)
__device__ float2 g_G[NB][MODES][COUT];             // mixed+scaled (Gc,Gs)

// ---- packed fp32x2 helpers ----
__device__ __forceinline__ ull pack2(float lo, float hi) {
    ull r; asm("mov.b64 %0, {%1, %2};" : "=l"(r) : "f"(lo), "f"(hi)); return r;
}
__device__ __forceinline__ float2 unpk(ull v) {
    float2 r; asm("mov.b64 {%0, %1}, %2;" : "=f"(r.x), "=f"(r.y) : "l"(v)); return r;
}
__device__ __forceinline__ void fma2(ull &acc, ull a, ull b) {
    asm("fma.rn.f32x2 %0, %1, %2, %0;" : "+l"(acc) : "l"(a), "l"(b));
}
__device__ __forceinline__ ull mul2(ull a, ull b) {
    ull r; asm("mul.rn.f32x2 %0, %1, %2;" : "=l"(r) : "l"(a), "l"(b)); return r;
}
__device__ __forceinline__ ull fma2r(ull a, ull b, ull c) {
    ull r; asm("fma.rn.f32x2 %0, %1, %2, %3;" : "=l"(r) : "l"(a), "l"(b), "l"(c)); return r;
}

__global__ void twiddle_init() {
    int j = blockIdx.x * blockDim.x + threadIdx.x;
    if (j < S_TOT) {
        float s, c;
        sincospif(j * (1.0f / 2048.0f), &s, &c);
        g_tw[j] = make_float2(c, s);
    }
}

// ---- Stage 1 (quad-folded forward DFT) ----
// Thread: 8 k x 2 i (acc 16 ull). High occupancy for latency hiding.
__global__ void __launch_bounds__(256, 3) kA(const float* __restrict__ x) {
    __shared__ float2 cmb[2][STG_A][CIN];   // [parity][s][i] = (Peff,Reff), 16 KB
    __shared__ float2 t2[STG_A][MODES];     // 4 KB
    int b = blockIdx.y, tid = threadIdx.x;
    int tx  = tid & 31;        // i in {2tx, 2tx+1}
    int kg  = (tid >> 5) & 3;  // k0 = kg*8
    int sub = tid >> 7;        // s-subset 0..1
    int k0 = kg * 8;
    int q00 = blockIdx.x * QPB_A;
    int r = tid >> 4, ig = tid & 15;   // loader role

    ull acc[8][2];
#pragma unroll
    for (int a = 0; a < 8; a++) { acc[a][0] = 0ull; acc[a][1] = 0ull; }

    const float* xb = x + (size_t)b * S_TOT * CIN;

    for (int st = 0; st < NSTG; ++st) {
        int q0 = q00 + st * STG_A;
        {   // load 4 mirror rows, combine into parity operands
            int s = q0 + 1 + r;
            float4 a1 = *(const float4*)&xb[(size_t)s * CIN + ig * 4];
            float4 a2 = *(const float4*)&xb[(size_t)(2048 - s) * CIN + ig * 4];
            float4 a3 = *(const float4*)&xb[(size_t)(2048 + s) * CIN + ig * 4];
            float4 a4 = *(const float4*)&xb[(size_t)(4096 - s) * CIN + ig * 4];
            float h = (s == 1024) ? 0.5f : 1.0f;
            float x1[4] = {a1.x, a1.y, a1.z, a1.w};
            float x2[4] = {a2.x, a2.y, a2.z, a2.w};
            float x3[4] = {a3.x, a3.y, a3.z, a3.w};
            float x4[4] = {a4.x, a4.y, a4.z, a4.w};
            float pe[4], re[4], po[4], ro[4];
#pragma unroll
            for (int j = 0; j < 4; ++j) {
                float P = x1[j] + x4[j], Q = x2[j] + x3[j];
                float R = x1[j] - x4[j], T = x3[j] - x2[j];
                pe[j] = h * (P + Q); re[j] = h * (R + T);
                po[j] = h * (P - Q); ro[j] = h * (R - T);
            }
            *(float4*)&cmb[0][r][ig * 4]     = make_float4(pe[0], re[0], pe[1], re[1]);
            *(float4*)&cmb[0][r][ig * 4 + 2] = make_float4(pe[2], re[2], pe[3], re[3]);
            *(float4*)&cmb[1][r][ig * 4]     = make_float4(po[0], ro[0], po[1], ro[1]);
            *(float4*)&cmb[1][r][ig * 4 + 2] = make_float4(po[2], ro[2], po[3], ro[3]);
        }
#pragma unroll
        for (int t = 0; t < 2; ++t) {   // twiddle tile (512 entries)
            int e = tid + t * 256;
            int sl = e >> 5, k = e & 31;
            t2[sl][k] = g_tw[((q0 + 1 + sl) * k) & SMASK];
        }
        __syncthreads();
#pragma unroll
        for (int slr = 0; slr < 8; ++slr) {
            int sl = sub * 8 + slr;
            ulonglong2 e2 = *(const ulonglong2*)&cmb[0][sl][2 * tx];  // i=2tx,2tx+1
            ulonglong2 o2 = *(const ulonglong2*)&cmb[1][sl][2 * tx];
            ull cE[2] = {e2.x, e2.y}, cO[2] = {o2.x, o2.y};
            ull tt[8];
#pragma unroll
            for (int m = 0; m < 4; ++m) {
                ulonglong2 tp = *(const ulonglong2*)&t2[sl][k0 + 2 * m];
                tt[2 * m] = tp.x; tt[2 * m + 1] = tp.y;
            }
#pragma unroll
            for (int kk = 0; kk < 8; ++kk) {
                fma2(acc[kk][0], tt[kk], (kk & 1) ? cO[0] : cE[0]);
                fma2(acc[kk][1], tt[kk], (kk & 1) ? cO[1] : cE[1]);
            }
        }
        __syncthreads();
    }
    int ch = blockIdx.x * SUBS + sub;
#pragma unroll
    for (int kk = 0; kk < 8; ++kk) {
        g_Yp[ch][b][k0 + kk][2 * tx]     = unpk(acc[kk][0]);
        g_Yp[ch][b][k0 + kk][2 * tx + 1] = unpk(acc[kk][1]);
    }
}

// ---- Stage 2: reduce partials + leftover rows {0,2048} + channel mix ----
__global__ void __launch_bounds__(64) kB(const float* __restrict__ W,
                                         const float* __restrict__ x) {
    int k = blockIdx.x, b = blockIdx.y, o = threadIdx.x;
    __shared__ float2 cs[CIN];
    {
        float2 a = make_float2(0.f, 0.f);
#pragma unroll
        for (int c = 0; c < NCH; ++c) {
            float2 v = g_Yp[c][b][k][o];
            a.x += v.x; a.y += v.y;
        }
        float x0    = x[(size_t)b * S_TOT * CIN + o];
        float x2048 = x[(size_t)b * S_TOT * CIN + 2048 * CIN + o];
        a.x += x0 + ((k & 1) ? -x2048 : x2048);
        cs[o] = a;
    }
    __syncthreads();
    const float* Wk = W + (size_t)k * CIN * COUT + o;
    float gc = 0.f, gs = 0.f;
#pragma unroll 8
    for (int i = 0; i < CIN; ++i) {
        float w = Wk[i * COUT];
        float2 v = cs[i];
        gc = fmaf(v.x, w, gc);
        gs = fmaf(v.y, w, gs);
    }
    float a = (k == 0 ? 1.0f : 2.0f) * (1.0f / (float)S_TOT);
    g_G[b][k][o] = make_float2(gc * a, gs * a);
}

// ---- Stage 3 (quad-folded inverse, register twiddle recurrence) ----
// Thread: 2 s (2 chains), 8 o interleaved {2og,2og+1}+{0,16,32,48}.
__global__ void __launch_bounds__(256, 2) kC(float* __restrict__ out) {
    __shared__ float2 gsh[MODES][COUT];     // 16 KB
    int b = blockIdx.y, tid = threadIdx.x;
    int q0 = blockIdx.x * QPB_C;
    {   // copy G for this batch
        const ulonglong2* src = (const ulonglong2*)&g_G[b][0][0];
        ulonglong2* dst = (ulonglong2*)gsh;
#pragma unroll
        for (int t = 0; t < (MODES * COUT / 2) / 256; ++t)
            dst[tid + t * 256] = src[tid + t * 256];
    }
    __syncthreads();

    int og = tid & 7, sg = tid >> 3;        // o base 2og, s = q0+1+2sg+{0,1}
    int sbase = q0 + 1 + 2 * sg;
    ull Wc[2], Aj[2], Bj[2];
#pragma unroll
    for (int j = 0; j < 2; ++j) {
        float s1, c1;
        sincospif((float)(sbase + j) * (1.0f / 2048.0f), &s1, &c1);
        Aj[j] = pack2(c1, s1);
        Bj[j] = pack2(-s1, c1);
        Wc[j] = pack2(1.0f, 0.0f);
    }
    ull acc[2][2][8];                       // [parity][s][o]
#pragma unroll
    for (int p = 0; p < 2; p++)
#pragma unroll
        for (int a = 0; a < 2; a++)
#pragma unroll
            for (int c = 0; c < 8; c++) acc[p][a][c] = 0ull;

#pragma unroll
    for (int k = 0; k < MODES; ++k) {
        ull gg[8];
#pragma unroll
        for (int m = 0; m < 4; ++m) {       // conflict-free: 8 lanes x 16B contig
            ulonglong2 gp = *(const ulonglong2*)&gsh[k][2 * og + 16 * m];
            gg[2 * m] = gp.x; gg[2 * m + 1] = gp.y;
        }
        const int par = k & 1;
#pragma unroll
        for (int j = 0; j < 2; ++j)
#pragma unroll
            for (int o = 0; o < 8; ++o)
                fma2(acc[par][j][o], Wc[j], gg[o]);
#pragma unroll
        for (int j = 0; j < 2; ++j) {       // step chains: W *= (c1, s1)
            float2 w = unpk(Wc[j]);
            ull t = mul2(pack2(w.x, w.x), Aj[j]);
            Wc[j] = fma2r(pack2(w.y, w.y), Bj[j], t);
        }
    }

    float* ob = out + (size_t)b * S_TOT * COUT;
#pragma unroll
    for (int ss = 0; ss < 2; ++ss) {
        int s = sbase + ss;
        float* r0 = &ob[(size_t)s * COUT];
        float* r1 = &ob[(size_t)(2048 - s) * COUT];
        float* r2 = &ob[(size_t)(2048 + s) * COUT];
        float* r3 = &ob[(size_t)(4096 - s) * COUT];
#pragma unroll
        for (int m = 0; m < 4; ++m) {
            int o0 = 2 * og + 16 * m;
            float2 Ea = unpk(acc[0][ss][2 * m]),     Oa = unpk(acc[1][ss][2 * m]);
            float2 Eb = unpk(acc[0][ss][2 * m + 1]), Ob = unpk(acc[1][ss][2 * m + 1]);
            *(float2*)&r0[o0] = make_float2(Ea.x + Ea.y + Oa.x + Oa.y,
                                            Eb.x + Eb.y + Ob.x + Ob.y);
            *(float2*)&r1[o0] = make_float2(Ea.x - Ea.y - Oa.x + Oa.y,
                                            Eb.x - Eb.y - Ob.x + Ob.y);
            *(float2*)&r2[o0] = make_float2(Ea.x + Ea.y - Oa.x - Oa.y,
                                            Eb.x + Eb.y - Ob.x - Ob.y);
            *(float2*)&r3[o0] = make_float2(Ea.x - Ea.y + Oa.x - Oa.y,
                                            Eb.x - Eb.y + Ob.x - Ob.y);
        }
    }

    // rows 0 and 2048 (sin terms vanish) — once per batch
    if (blockIdx.x == 0 && tid < COUT) {
        float a0 = 0.f, a1 = 0.f;
#pragma unroll
        for (int k = 0; k < MODES; ++k) {
            float gc = gsh[k][tid].x;
            a0 += gc;
            a1 += (k & 1) ? -gc : gc;
        }
        ob[tid] = a0;
        ob[(size_t)2048 * COUT + tid] = a1;
    }
}

extern "C" void kernel_launch(void* const* d_in, const int* in_sizes, int n_in,
                              void* d_out, int out_size) {
    const float* x = (const float*)d_in[0];   // [64, 4096, 64]
    const float* W = (const float*)d_in[1];   // [32, 64, 64]
    float* out = (float*)d_out;               // [64, 4096, 64]
    (void)in_sizes; (void)n_in; (void)out_size;

    twiddle_init<<<16, 256>>>();
    kA<<<dim3(CH_A, NB), 256>>>(x);
    kB<<<dim3(MODES, NB), 64>>>(W, x);
    kC<<<dim3(1024 / QPB_C, NB), 256>>>(out);
}

// round 9
// speedup vs baseline: 1.2303x; 1.2303x over previous
#include <cuda_runtime.h>

// SpectralConv1D: out = irfft( pad( rfft(x)[:, :32, :] @ W ) )
// Quad-folded trig transforms (4x via mirror symmetry over
// {s, 2048-s, 2048+s, 4096-s}). B=64, S=4096, Cin=Cout=64, MODES=32.
// kA: pipelined, twiddles from transposed table (coalesced sectors).
// kC: parity-split register twiddle chains (double-angle step every 2 k).

#define S_TOT   4096
#define SMASK   4095
#define CIN     64
#define COUT    64
#define MODES   32
#define NB      64
#define CH_A    4
#define SUBS    4
#define NCH     (CH_A*SUBS)
#define QPB_A   256
#define STG_A   16
#define NSTG    (QPB_A/STG_A)
#define QPB_C   32

typedef unsigned long long ull;

__device__ float2 g_tw2[1025][MODES];               // (cos,sin)(2*pi*s*k/4096)
__device__ float2 g_Yp[NCH][NB][MODES][CIN];        // split-K partials (Cr,Si)
__device__ float2 g_G[NB][MODES][COUT];             // mixed+scaled (Gc,Gs)

// ---- packed fp32x2 helpers ----
__device__ __forceinline__ ull pack2(float lo, float hi) {
    ull r; asm("mov.b64 %0, {%1, %2};" : "=l"(r) : "f"(lo), "f"(hi)); return r;
}
__device__ __forceinline__ float2 unpk(ull v) {
    float2 r; asm("mov.b64 {%0, %1}, %2;" : "=f"(r.x), "=f"(r.y) : "l"(v)); return r;
}
__device__ __forceinline__ void fma2(ull &acc, ull a, ull b) {
    asm("fma.rn.f32x2 %0, %1, %2, %0;" : "+l"(acc) : "l"(a), "l"(b));
}
__device__ __forceinline__ ull mul2(ull a, ull b) {
    ull r; asm("mul.rn.f32x2 %0, %1, %2;" : "=l"(r) : "l"(a), "l"(b)); return r;
}
__device__ __forceinline__ ull fma2r(ull a, ull b, ull c) {
    ull r; asm("fma.rn.f32x2 %0, %1, %2, %3;" : "=l"(r) : "l"(a), "l"(b), "l"(c)); return r;
}

__global__ void twiddle_init() {
    int j = blockIdx.x * blockDim.x + threadIdx.x;
    if (j < 1025 * MODES) {
        int s = j >> 5, k = j & 31;
        float sn, cs;
        sincospif((float)((s * k) & SMASK) * (1.0f / 2048.0f), &sn, &cs);
        g_tw2[s][k] = make_float2(cs, sn);
    }
}

// ---- Stage 1 (quad-folded forward DFT, pipelined) ----
// Cr_k += cos(th)*[P + (-1)^k Q],  Si_k += sin(th)*[R + (-1)^k T]
__global__ void __launch_bounds__(256, 2) kA(const float* __restrict__ x) {
    __shared__ float2 cmb[2][2][STG_A][CIN];  // [buf][parity][s][i], 32 KB
    __shared__ float2 t2[2][STG_A][MODES];    // 8 KB
    int b = blockIdx.y, tid = threadIdx.x;
    int tx  = tid & 15;        // i in {tx, tx+16, tx+32, tx+48}
    int kg  = (tid >> 4) & 3;  // k0 = kg*8
    int sub = tid >> 6;        // s-subset 0..3
    int k0 = kg * 8;
    int q00 = blockIdx.x * QPB_A;
    int r = tid >> 4, ig = tid & 15;   // loader role
    int sl0 = tid >> 5, kk0 = tid & 31;  // twiddle loader (warp-contiguous in k)

    ull acc[8][4];
#pragma unroll
    for (int a = 0; a < 8; a++)
#pragma unroll
        for (int c = 0; c < 4; c++) acc[a][c] = 0ull;

    const float* xb = x + (size_t)b * S_TOT * CIN;

    float4 a1, a2, a3, a4;
    float2 tw0, tw1;
    {   // prologue: prefetch stage 0
        int s = q00 + 1 + r;
        a1 = *(const float4*)&xb[(size_t)s * CIN + ig * 4];
        a2 = *(const float4*)&xb[(size_t)(2048 - s) * CIN + ig * 4];
        a3 = *(const float4*)&xb[(size_t)(2048 + s) * CIN + ig * 4];
        a4 = *(const float4*)&xb[(size_t)(4096 - s) * CIN + ig * 4];
        tw0 = g_tw2[q00 + 1 + sl0][kk0];
        tw1 = g_tw2[q00 + 1 + sl0 + 8][kk0];
    }

    for (int st = 0; st < NSTG; ++st) {
        int buf = st & 1;
        int q0 = q00 + st * STG_A;
        {   // combine prefetched rows -> parity operands, store to smem
            int s = q0 + 1 + r;
            float h = (s == 1024) ? 0.5f : 1.0f;
            float x1[4] = {a1.x, a1.y, a1.z, a1.w};
            float x2[4] = {a2.x, a2.y, a2.z, a2.w};
            float x3[4] = {a3.x, a3.y, a3.z, a3.w};
            float x4[4] = {a4.x, a4.y, a4.z, a4.w};
            float pe[4], re[4], po[4], ro[4];
#pragma unroll
            for (int j = 0; j < 4; ++j) {
                float P = x1[j] + x4[j], Q = x2[j] + x3[j];
                float R = x1[j] - x4[j], T = x3[j] - x2[j];
                pe[j] = h * (P + Q); re[j] = h * (R + T);
                po[j] = h * (P - Q); ro[j] = h * (R - T);
            }
            *(float4*)&cmb[buf][0][r][ig * 4]     = make_float4(pe[0], re[0], pe[1], re[1]);
            *(float4*)&cmb[buf][0][r][ig * 4 + 2] = make_float4(pe[2], re[2], pe[3], re[3]);
            *(float4*)&cmb[buf][1][r][ig * 4]     = make_float4(po[0], ro[0], po[1], ro[1]);
            *(float4*)&cmb[buf][1][r][ig * 4 + 2] = make_float4(po[2], ro[2], po[3], ro[3]);
            t2[buf][sl0][kk0]     = tw0;
            t2[buf][sl0 + 8][kk0] = tw1;
        }
        __syncthreads();
        if (st + 1 < NSTG) {   // prefetch next stage (overlaps compute below)
            int s = q0 + STG_A + 1 + r;
            a1 = *(const float4*)&xb[(size_t)s * CIN + ig * 4];
            a2 = *(const float4*)&xb[(size_t)(2048 - s) * CIN + ig * 4];
            a3 = *(const float4*)&xb[(size_t)(2048 + s) * CIN + ig * 4];
            a4 = *(const float4*)&xb[(size_t)(4096 - s) * CIN + ig * 4];
            tw0 = g_tw2[q0 + STG_A + 1 + sl0][kk0];
            tw1 = g_tw2[q0 + STG_A + 1 + sl0 + 8][kk0];
        }
#pragma unroll
        for (int slr = 0; slr < 4; ++slr) {
            int sl = sub * 4 + slr;
            ull cE[4], cO[4];
#pragma unroll
            for (int ii = 0; ii < 4; ++ii) {
                cE[ii] = *(const ull*)&cmb[buf][0][sl][tx + 16 * ii];
                cO[ii] = *(const ull*)&cmb[buf][1][sl][tx + 16 * ii];
            }
            ull tt[8];
#pragma unroll
            for (int m = 0; m < 4; ++m) {
                ulonglong2 tp = *(const ulonglong2*)&t2[buf][sl][k0 + 2 * m];
                tt[2 * m] = tp.x; tt[2 * m + 1] = tp.y;
            }
#pragma unroll
            for (int kk = 0; kk < 8; ++kk)
#pragma unroll
                for (int ii = 0; ii < 4; ++ii)
                    fma2(acc[kk][ii], tt[kk], (kk & 1) ? cO[ii] : cE[ii]);
        }
        // no second sync: STS(st+2) into this buf is separated from all
        // compute(st) reads by the barrier at stage st+1.
    }
    int ch = blockIdx.x * SUBS + sub;
#pragma unroll
    for (int kk = 0; kk < 8; ++kk)
#pragma unroll
        for (int ii = 0; ii < 4; ++ii)
            g_Yp[ch][b][k0 + kk][tx + 16 * ii] = unpk(acc[kk][ii]);
}

// ---- Stage 2: reduce partials + leftover rows {0,2048} + channel mix ----
__global__ void __launch_bounds__(64) kB(const float* __restrict__ W,
                                         const float* __restrict__ x) {
    int k = blockIdx.x, b = blockIdx.y, o = threadIdx.x;
    __shared__ float2 cs[CIN];
    {
        float2 a = make_float2(0.f, 0.f);
#pragma unroll
        for (int c = 0; c < NCH; ++c) {
            float2 v = g_Yp[c][b][k][o];
            a.x += v.x; a.y += v.y;
        }
        float x0    = x[(size_t)b * S_TOT * CIN + o];
        float x2048 = x[(size_t)b * S_TOT * CIN + 2048 * CIN + o];
        a.x += x0 + ((k & 1) ? -x2048 : x2048);
        cs[o] = a;
    }
    __syncthreads();
    const float* Wk = W + (size_t)k * CIN * COUT + o;
    float gc = 0.f, gs = 0.f;
#pragma unroll 8
    for (int i = 0; i < CIN; ++i) {
        float w = Wk[i * COUT];
        float2 v = cs[i];
        gc = fmaf(v.x, w, gc);
        gs = fmaf(v.y, w, gs);
    }
    float a = (k == 0 ? 1.0f : 2.0f) * (1.0f / (float)S_TOT);
    g_G[b][k][o] = make_float2(gc * a, gs * a);
}

// ---- Stage 3 (quad-folded inverse, parity-split twiddle chains) ----
// Thread: 2 s, o in {2tx,2tx+1,2tx+32,2tx+33}. Even/odd-k chains stepped by
// the double angle once per 2 modes -> fewer issue slots per fma2.
__global__ void __launch_bounds__(256, 3) kC(float* __restrict__ out) {
    __shared__ float2 gsh[MODES][COUT];     // 16 KB
    int b = blockIdx.y, tid = threadIdx.x;
    int q0 = blockIdx.x * QPB_C;
    {   // copy G for this batch
        const ulonglong2* src = (const ulonglong2*)&g_G[b][0][0];
        ulonglong2* dst = (ulonglong2*)gsh;
#pragma unroll
        for (int t = 0; t < (MODES * COUT / 2) / 256; ++t)
            dst[tid + t * 256] = src[tid + t * 256];
    }
    __syncthreads();

    int tx = tid & 15, ty = tid >> 4;
    int sbase = q0 + 1 + 2 * ty;            // 2 consecutive s
    ull We[2], Wo[2], A2[2], B2[2];
#pragma unroll
    for (int j = 0; j < 2; ++j) {
        float s1, c1;
        sincospif((float)(sbase + j) * (1.0f / 2048.0f), &s1, &c1);
        We[j] = pack2(1.0f, 0.0f);
        Wo[j] = pack2(c1, s1);
        float c2 = fmaf(-2.0f * s1, s1, 1.0f);
        float s2 = 2.0f * s1 * c1;
        A2[j] = pack2(c2, s2);
        B2[j] = pack2(-s2, c2);
    }
    ull acc[2][2][4];                       // [parity][s][o]
#pragma unroll
    for (int p = 0; p < 2; p++)
#pragma unroll
        for (int a = 0; a < 2; a++)
#pragma unroll
            for (int c = 0; c < 4; c++) acc[p][a][c] = 0ull;

#pragma unroll
    for (int kp = 0; kp < MODES / 2; ++kp) {
        {   // even mode k = 2kp -> E accumulators
            ulonglong2 g0 = *(const ulonglong2*)&gsh[2 * kp][2 * tx];
            ulonglong2 g1 = *(const ulonglong2*)&gsh[2 * kp][2 * tx + 32];
            ull gg[4] = {g0.x, g0.y, g1.x, g1.y};
#pragma unroll
            for (int j = 0; j < 2; ++j)
#pragma unroll
                for (int o = 0; o < 4; ++o)
                    fma2(acc[0][j][o], We[j], gg[o]);
        }
        {   // odd mode k = 2kp+1 -> O accumulators
            ulonglong2 g0 = *(const ulonglong2*)&gsh[2 * kp + 1][2 * tx];
            ulonglong2 g1 = *(const ulonglong2*)&gsh[2 * kp + 1][2 * tx + 32];
            ull gg[4] = {g0.x, g0.y, g1.x, g1.y};
#pragma unroll
            for (int j = 0; j < 2; ++j)
#pragma unroll
                for (int o = 0; o < 4; ++o)
                    fma2(acc[1][j][o], Wo[j], gg[o]);
        }
#pragma unroll
        for (int j = 0; j < 2; ++j) {       // step both chains by double angle
            float2 we = unpk(We[j]);
            We[j] = fma2r(pack2(we.y, we.y), B2[j], mul2(pack2(we.x, we.x), A2[j]));
            float2 wo = unpk(Wo[j]);
            Wo[j] = fma2r(pack2(wo.y, wo.y), B2[j], mul2(pack2(wo.x, wo.x), A2[j]));
        }
    }

    float* ob = out + (size_t)b * S_TOT * COUT;
#pragma unroll
    for (int ss = 0; ss < 2; ++ss) {
        int s = sbase + ss;
        float* r0 = &ob[(size_t)s * COUT];
        float* r1 = &ob[(size_t)(2048 - s) * COUT];
        float* r2 = &ob[(size_t)(2048 + s) * COUT];
        float* r3 = &ob[(size_t)(4096 - s) * COUT];
#pragma unroll
        for (int g = 0; g < 2; ++g) {
            int j = 2 * g, o0 = 2 * tx + 32 * g;
            float2 Ea = unpk(acc[0][ss][j]),     Oa = unpk(acc[1][ss][j]);
            float2 Eb = unpk(acc[0][ss][j + 1]), Ob = unpk(acc[1][ss][j + 1]);
            *(float2*)&r0[o0] = make_float2(Ea.x + Ea.y + Oa.x + Oa.y,
                                            Eb.x + Eb.y + Ob.x + Ob.y);
            *(float2*)&r1[o0] = make_float2(Ea.x - Ea.y - Oa.x + Oa.y,
                                            Eb.x - Eb.y - Ob.x + Ob.y);
            *(float2*)&r2[o0] = make_float2(Ea.x + Ea.y - Oa.x - Oa.y,
                                            Eb.x + Eb.y - Ob.x - Ob.y);
            *(float2*)&r3[o0] = make_float2(Ea.x - Ea.y + Oa.x - Oa.y,
                                            Eb.x - Eb.y + Ob.x - Ob.y);
        }
    }

    // rows 0 and 2048 (sin terms vanish) — once per batch
    if (blockIdx.x == 0 && tid < COUT) {
        float a0 = 0.f, a1 = 0.f;
#pragma unroll
        for (int k = 0; k < MODES; ++k) {
            float gc = gsh[k][tid].x;
            a0 += gc;
            a1 += (k & 1) ? -gc : gc;
        }
        ob[tid] = a0;
        ob[(size_t)2048 * COUT + tid] = a1;
    }
}

extern "C" void kernel_launch(void* const* d_in, const int* in_sizes, int n_in,
                              void* d_out, int out_size) {
    const float* x = (const float*)d_in[0];   // [64, 4096, 64]
    const float* W = (const float*)d_in[1];   // [32, 64, 64]
    float* out = (float*)d_out;               // [64, 4096, 64]
    (void)in_sizes; (void)n_in; (void)out_size;

    twiddle_init<<<129, 256>>>();
    kA<<<dim3(CH_A, NB), 256>>>(x);
    kB<<<dim3(MODES, NB), 64>>>(W, x);
    kC<<<dim3(1024 / QPB_C, NB), 256>>>(out);
}